// round 13
// baseline (speedup 1.0000x reference)
#include <cuda_runtime.h>
#include <math.h>
#include <stdint.h>

#define BB    128
#define SEQ   64
#define CH    256
#define PARTS 16
#define NT    512

#define XST_STR 261                 // 261 % 32 = 5 -> conflict-free quad reads
#define HT_STR  133                 // 133 % 32 = 5
#define A_STR   36                  // 36 % 32 = 4  -> conflict-free A frags

#define XST_OFF 0                               // [68 t][261], data t = s+2
#define HT_OFF  (68 * XST_STR)                  // 17748: [66 t][133], data t = s+1
#define AB_OFF  26528                           // 3 x [256][36] raw weight stages
#define ABUF_FL 9216
#define PR_OFF  (AB_OFF + ABUF_FL)              // 35744: K-split partials (in stage 1)
#define PART_OFF (AB_OFF + 2*ABUF_FL)           // 44960: final partials (in stage 2)
#define SMEM_FL  (AB_OFF + 3*ABUF_FL)           // 54176 fl = 216704 B

__device__ __forceinline__ uint32_t smem_u32(const void* p) {
    uint32_t a;
    asm("{ .reg .u64 t; cvta.to.shared.u64 t, %1; cvt.u32.u64 %0, t; }"
        : "=r"(a) : "l"(p));
    return a;
}
__device__ __forceinline__ float leaky(float v) { return (v > 0.f) ? v : 0.01f * v; }
__device__ __forceinline__ float sigmoidf_fast(float v) {
    return 1.0f / (1.0f + __expf(-v));
}
__device__ __forceinline__ void cpa16(uint32_t dst, const void* src) {
    asm volatile("cp.async.cg.shared.global [%0], [%1], 16;" :: "r"(dst), "l"(src));
}
#define CP_COMMIT() asm volatile("cp.async.commit_group;" ::: "memory")
#define CP_WAIT0()  asm volatile("cp.async.wait_group 0;" ::: "memory")
#define CP_WAIT1()  asm volatile("cp.async.wait_group 1;" ::: "memory")

// D[16x8] += A[16x8] * B[8x8]  (tf32: HW truncates raw fp32 operand bits)
__device__ __forceinline__ void mma8(float* d, const uint32_t* a,
                                     uint32_t b0, uint32_t b1) {
    asm volatile(
        "mma.sync.aligned.m16n8k8.row.col.f32.tf32.tf32.f32 "
        "{%0,%1,%2,%3}, {%4,%5,%6,%7}, {%8,%9}, {%0,%1,%2,%3};"
        : "+f"(d[0]), "+f"(d[1]), "+f"(d[2]), "+f"(d[3])
        : "r"(a[0]), "r"(a[1]), "r"(a[2]), "r"(a[3]), "r"(b0), "r"(b1));
}

__device__ __forceinline__ float pool_val(int s, float x0, float x1, float x2,
                                          float x3, float x4, float l1, float l2) {
    float avg3 = (x1 + x2 + x3) * (1.0f / 3.0f);
    float avg5 = (x0 + x1 + x2 + x3 + x4) * 0.2f;
    float mx3 = x2;
    if (s >= 1)  mx3 = fmaxf(mx3, x1);
    if (s <= 62) mx3 = fmaxf(mx3, x3);
    float mx5 = mx3;
    if (s >= 2)  mx5 = fmaxf(mx5, x0);
    if (s <= 61) mx5 = fmaxf(mx5, x4);
    return (avg3 + mx3) * sigmoidf_fast(l1) + (avg5 + mx5) * sigmoidf_fast(l2);
}

__global__ void __launch_bounds__(NT, 1)
mtb_mma3_kernel(const float* __restrict__ x,
                const float* __restrict__ W1a,
                const float* __restrict__ W1b,
                const float* __restrict__ W2a,
                const float* __restrict__ W2b,
                float* __restrict__ out)
{
    extern __shared__ float smem[];
    float* xst = smem + XST_OFF;     // time-major x, exact fp32
    float* ht  = smem + HT_OFF;      // time-major h (raw fp32), cols 0..63 h1, 64..127 h2
    const uint32_t ab_addr = smem_u32(smem + AB_OFF);

    const int tid = threadIdx.x;
    const int wid = tid >> 5;
    const int l   = tid & 31;
    const int b   = blockIdx.x >> 4;
    const int p   = blockIdx.x & 15;

    // ---- zero pads ----
    if (tid < 256) {
        xst[0 * XST_STR + tid] = 0.f;
        xst[1 * XST_STR + tid] = 0.f;
        xst[66 * XST_STR + tid] = 0.f;
        xst[67 * XST_STR + tid] = 0.f;
    }
    if (tid < 128) {
        ht[0 * HT_STR + tid] = 0.f;
        ht[65 * HT_STR + tid] = 0.f;
    }

    const float* Wa1 = W1a + (size_t)p * (64 * CH * 3);   // [64][768]
    const float* Wa2 = W2a + (size_t)p * (64 * CH * 3);
    const float* Wb1 = W1b + (size_t)p * (CH * 64);       // [256][64]
    const float* Wb2 = W2b + (size_t)p * (CH * 192);      // [256][192]

    // ---- prefetch phase-1 chunks 0,1 into stages 0,1 ----
    #pragma unroll
    for (int it = 0; it < 2; it++) {
        int idx = it * NT + tid;
        int row = idx >> 3, col4 = idx & 7;
        const float* src = ((row < 64) ? (Wa1 + row * 768)
                                       : (Wa2 + (row - 64) * 768)) + col4 * 4;
        cpa16(ab_addr + (uint32_t)(row * A_STR + col4 * 4) * 4u, src);
    }
    CP_COMMIT();

    // ---- load x slice (exact fp32, time-major): xst[s+2][c] ----
    {
        const int c  = tid & 255;
        const int sh = tid >> 8;
        const float* xb = x + (size_t)b * (SEQ * CH * PARTS) + p + (size_t)c * PARTS;
        float* xcol = xst + (sh * 32 + 2) * XST_STR + c;
        #pragma unroll 8
        for (int s = 0; s < 32; s++)
            xcol[s * XST_STR] = xb[(size_t)(sh * 32 + s) * (CH * PARTS)];
    }

    #pragma unroll
    for (int it = 0; it < 2; it++) {
        int idx = it * NT + tid;
        int row = idx >> 3, col4 = idx & 7;
        const float* src = ((row < 64) ? (Wa1 + row * 768)
                                       : (Wa2 + (row - 64) * 768)) + 32 + col4 * 4;
        cpa16(ab_addr + (uint32_t)(ABUF_FL + row * A_STR + col4 * 4) * 4u, src);
    }
    CP_COMMIT();

    // ================= Phase 1: D1[128 r][64 s], K=768 (kk = c*3+k) =============
    const int ks1   = wid >> 3;
    const int mrow1 = (wid >> 1) & 3;
    const int nh1   = wid & 1;

    float acc[2][4][4];
    #pragma unroll
    for (int i = 0; i < 2; i++)
        #pragma unroll
        for (int j = 0; j < 4; j++)
            #pragma unroll
            for (int t = 0; t < 4; t++) acc[i][j][t] = 0.f;

    for (int g = 0; g < 24; g++) {
        if (g + 1 < 24) { CP_WAIT1(); } else { CP_WAIT0(); }
        __syncthreads();          // stage g visible to all; compute g-1 done everywhere

        if (g + 2 < 24) {
            const int st = (g + 2) % 3;
            #pragma unroll
            for (int it = 0; it < 2; it++) {
                int idx = it * NT + tid;
                int row = idx >> 3, col4 = idx & 7;
                const float* src = ((row < 64) ? (Wa1 + row * 768)
                                               : (Wa2 + (row - 64) * 768))
                                   + (g + 2) * 32 + col4 * 4;
                cpa16(ab_addr + (uint32_t)(st * ABUF_FL + row * A_STR + col4 * 4) * 4u, src);
            }
            CP_COMMIT();
        }

        const float* Ar = smem + AB_OFF + (g % 3) * ABUF_FL;
        #pragma unroll
        for (int q2 = 0; q2 < 2; q2++) {
            int qq   = ks1 * 2 + q2;
            int kloc = qq * 8 + (l & 3);
            int kg   = g * 32 + kloc;
            int c0 = kg / 3,       k0 = kg - 3 * c0;
            int c1 = (kg + 4) / 3, k1 = (kg + 4) - 3 * c1;
            const float* bp0 = xst + (nh1 * 32 + (l >> 2) + k0 + 1) * XST_STR + c0;
            const float* bp1 = xst + (nh1 * 32 + (l >> 2) + k1 + 1) * XST_STR + c1;
            uint32_t a[2][4];
            #pragma unroll
            for (int msub = 0; msub < 2; msub++) {
                const float* ap = Ar + (mrow1 * 32 + msub * 16 + (l >> 2)) * A_STR + kloc;
                a[msub][0] = __float_as_uint(ap[0]);
                a[msub][1] = __float_as_uint(ap[8 * A_STR]);
                a[msub][2] = __float_as_uint(ap[4]);
                a[msub][3] = __float_as_uint(ap[8 * A_STR + 4]);
            }
            #pragma unroll
            for (int n8 = 0; n8 < 4; n8++) {
                uint32_t b0 = __float_as_uint(bp0[n8 * 8 * XST_STR]);
                uint32_t b1 = __float_as_uint(bp1[n8 * 8 * XST_STR]);
                mma8(acc[0][n8], a[0], b0, b1);
                mma8(acc[1][n8], a[1], b0, b1);
            }
        }
    }

    // ---- K-split merge: ks1==1 warps publish partials (stage-1 region, free) ----
    {
        float4* pb = reinterpret_cast<float4*>(smem + PR_OFF);
        if (ks1 == 1) {
            int base = ((wid - 8) * 32 + l) * 8;
            #pragma unroll
            for (int msub = 0; msub < 2; msub++)
                #pragma unroll
                for (int n8 = 0; n8 < 4; n8++)
                    pb[base + msub * 4 + n8] =
                        make_float4(acc[msub][n8][0], acc[msub][n8][1],
                                    acc[msub][n8][2], acc[msub][n8][3]);
        }
    }
    __syncthreads();

    // ---- prefetch phase-2 tile 0 (Wb1 cols 0..31) into stage 0 ----
    #pragma unroll
    for (int it = 0; it < 4; it++) {
        int idx = it * NT + tid;
        int row = idx >> 3, col4 = idx & 7;
        cpa16(ab_addr + (uint32_t)(row * A_STR + col4 * 4) * 4u,
              Wb1 + row * 64 + col4 * 4);
    }
    CP_COMMIT();

    // ---- epilogue 1 (ks1==0 warps): merge + leaky -> ht (raw fp32, time-major) ----
    if (ks1 == 0) {
        const float4* pb = reinterpret_cast<const float4*>(smem + PR_OFF);
        int base = (wid * 32 + l) * 8;
        #pragma unroll
        for (int msub = 0; msub < 2; msub++) {
            #pragma unroll
            for (int n8 = 0; n8 < 4; n8++) {
                float4 t = pb[base + msub * 4 + n8];
                float d0 = acc[msub][n8][0] + t.x;
                float d1 = acc[msub][n8][1] + t.y;
                float d2 = acc[msub][n8][2] + t.z;
                float d3 = acc[msub][n8][3] + t.w;
                int r    = mrow1 * 32 + msub * 16 + (l >> 2);
                int scol = nh1 * 32 + n8 * 8 + 2 * (l & 3);
                float* h0 = ht + (scol + 1) * HT_STR + r;
                float* h1 = ht + (scol + 2) * HT_STR + r;
                h0[0] = leaky(d0);
                h1[0] = leaky(d1);
                h0[8] = leaky(d2);
                h1[8] = leaky(d3);
            }
        }
    }
    __syncthreads();   // ht visible; PR reads done

    // ---- prefetch phase-2 tile 1 into stage 1 (PR region now free) ----
    #pragma unroll
    for (int it = 0; it < 4; it++) {
        int idx = it * NT + tid;
        int row = idx >> 3, col4 = idx & 7;
        cpa16(ab_addr + (uint32_t)(ABUF_FL + row * A_STR + col4 * 4) * 4u,
              Wb1 + row * 64 + 32 + col4 * 4);
    }
    CP_COMMIT();

    // ================= Phase 2: logits1 (K=64) + logits2 (K=192) ===============
    const int mrow2 = wid >> 1;     // 0..7 over 256 c-rows
    const int nh2   = wid & 1;

    float acc1[2][4][4], acc2[2][4][4];
    #pragma unroll
    for (int i = 0; i < 2; i++)
        #pragma unroll
        for (int j = 0; j < 4; j++)
            #pragma unroll
            for (int t = 0; t < 4; t++) { acc1[i][j][t] = 0.f; acc2[i][j][t] = 0.f; }

    for (int j = 0; j < 8; j++) {
        if (j + 1 < 8) { CP_WAIT1(); } else { CP_WAIT0(); }
        __syncthreads();

        if (j + 2 < 8) {
            const int jn   = j + 2;
            const int st   = jn % 3;
            const float* base = (jn < 2) ? Wb1 : Wb2;
            const int rstr = (jn < 2) ? 64 : 192;
            const int koff = (jn < 2) ? jn * 32 : (jn - 2) * 32;
            #pragma unroll
            for (int it = 0; it < 4; it++) {
                int idx = it * NT + tid;
                int row = idx >> 3, col4 = idx & 7;
                cpa16(ab_addr + (uint32_t)(st * ABUF_FL + row * A_STR + col4 * 4) * 4u,
                      base + row * rstr + koff + col4 * 4);
            }
            CP_COMMIT();
        }

        const float* Ar = smem + AB_OFF + (j % 3) * ABUF_FL;
        if (j < 2) {
            // branch 1: B = h1 (ht cols 0..63)
            #pragma unroll
            for (int qq = 0; qq < 4; qq++) {
                int kloc = qq * 8 + (l & 3);
                int h    = j * 32 + kloc;
                const float* bp = ht + (nh2 * 32 + (l >> 2) + 1) * HT_STR + h;
                uint32_t a[2][4];
                #pragma unroll
                for (int msub = 0; msub < 2; msub++) {
                    const float* ap = Ar + (mrow2 * 32 + msub * 16 + (l >> 2)) * A_STR + kloc;
                    a[msub][0] = __float_as_uint(ap[0]);
                    a[msub][1] = __float_as_uint(ap[8 * A_STR]);
                    a[msub][2] = __float_as_uint(ap[4]);
                    a[msub][3] = __float_as_uint(ap[8 * A_STR + 4]);
                }
                #pragma unroll
                for (int n8 = 0; n8 < 4; n8++) {
                    uint32_t b0 = __float_as_uint(bp[n8 * 8 * HT_STR]);
                    uint32_t b1 = __float_as_uint(bp[n8 * 8 * HT_STR + 4]);
                    mma8(acc1[0][n8], a[0], b0, b1);
                    mma8(acc1[1][n8], a[1], b0, b1);
                }
            }
        } else {
            // branch 2: B = h2 shifted windows (ht cols 64..127), kk = h*3+k
            const int gj = j - 2;
            #pragma unroll
            for (int qq = 0; qq < 4; qq++) {
                int kloc = qq * 8 + (l & 3);
                int kg   = gj * 32 + kloc;
                int h0 = kg / 3,       k0 = kg - 3 * h0;
                int h1 = (kg + 4) / 3, k1 = (kg + 4) - 3 * h1;
                const float* bp0 = ht + (nh2 * 32 + (l >> 2) + k0) * HT_STR + 64 + h0;
                const float* bp1 = ht + (nh2 * 32 + (l >> 2) + k1) * HT_STR + 64 + h1;
                uint32_t a[2][4];
                #pragma unroll
                for (int msub = 0; msub < 2; msub++) {
                    const float* ap = Ar + (mrow2 * 32 + msub * 16 + (l >> 2)) * A_STR + kloc;
                    a[msub][0] = __float_as_uint(ap[0]);
                    a[msub][1] = __float_as_uint(ap[8 * A_STR]);
                    a[msub][2] = __float_as_uint(ap[4]);
                    a[msub][3] = __float_as_uint(ap[8 * A_STR + 4]);
                }
                #pragma unroll
                for (int n8 = 0; n8 < 4; n8++) {
                    uint32_t b0 = __float_as_uint(bp0[n8 * 8 * HT_STR]);
                    uint32_t b1 = __float_as_uint(bp1[n8 * 8 * HT_STR]);
                    mma8(acc2[0][n8], a[0], b0, b1);
                    mma8(acc2[1][n8], a[1], b0, b1);
                }
            }
        }
    }

    // ---- epilogue 2: pools + sigmoid gates + combine + temporal max ----
    float rmax[4] = {-INFINITY, -INFINITY, -INFINITY, -INFINITY};
    #pragma unroll
    for (int msub = 0; msub < 2; msub++) {
        #pragma unroll
        for (int n8 = 0; n8 < 4; n8++) {
            int R0 = mrow2 * 32 + msub * 16 + (l >> 2);
            int s0 = nh2 * 32 + n8 * 8 + 2 * (l & 3);
            #pragma unroll
            for (int rh = 0; rh < 2; rh++) {
                int c = R0 + rh * 8;
                const float* xr = xst + s0 * XST_STR + c;
                float w0 = xr[0],            w1 = xr[XST_STR];
                float w2 = xr[2 * XST_STR],  w3 = xr[3 * XST_STR];
                float w4 = xr[4 * XST_STR],  w5 = xr[5 * XST_STR];
                float v0 = pool_val(s0, w0, w1, w2, w3, w4,
                                    acc1[msub][n8][rh * 2], acc2[msub][n8][rh * 2]);
                float v1 = pool_val(s0 + 1, w1, w2, w3, w4, w5,
                                    acc1[msub][n8][rh * 2 + 1], acc2[msub][n8][rh * 2 + 1]);
                rmax[msub * 2 + rh] = fmaxf(rmax[msub * 2 + rh], fmaxf(v0, v1));
            }
        }
    }
    #pragma unroll
    for (int off = 1; off <= 2; off <<= 1) {
        #pragma unroll
        for (int i = 0; i < 4; i++)
            rmax[i] = fmaxf(rmax[i], __shfl_xor_sync(0xffffffffu, rmax[i], off));
    }
    {
        int idx = l & 3;
        float v = (idx == 0) ? rmax[0] : (idx == 1) ? rmax[1]
                 : (idx == 2) ? rmax[2] : rmax[3];
        int row = mrow2 * 32 + 16 * (idx >> 1) + 8 * (idx & 1) + (l >> 2);
        smem[PART_OFF + nh2 * 256 + row] = v;
    }
    __syncthreads();
    if (tid < 256)
        out[(size_t)blockIdx.x * CH + tid] =
            fmaxf(smem[PART_OFF + tid], smem[PART_OFF + 256 + tid]);
}

extern "C" void kernel_launch(void* const* d_in, const int* in_sizes, int n_in,
                              void* d_out, int out_size)
{
    const float* x   = (const float*)d_in[0];
    const float* W1a = (const float*)d_in[1];
    const float* W1b = (const float*)d_in[2];
    const float* W2a = (const float*)d_in[3];
    const float* W2b = (const float*)d_in[4];
    float* out = (float*)d_out;

    const int smem_bytes = SMEM_FL * (int)sizeof(float);   // 216704
    cudaFuncSetAttribute(mtb_mma3_kernel, cudaFuncAttributeMaxDynamicSharedMemorySize,
                         smem_bytes);
    mtb_mma3_kernel<<<BB * PARTS, NT, smem_bytes>>>(x, W1a, W1b, W2a, W2b, out);
}

// round 15
// speedup vs baseline: 1.0783x; 1.0783x over previous
#include <cuda_runtime.h>
#include <math.h>
#include <stdint.h>

#define BB    128
#define SEQ   64
#define CH    256
#define PARTS 16
#define NT    512

#define XST_STR 261                 // 261 % 32 = 5 -> conflict-free quad reads
#define HT_STR  133                 // 133 % 32 = 5
#define A_STR   36                  // 36 % 32 = 4  -> conflict-free A frags

#define XST_OFF 0                               // [68 t][261], data t = s+2
#define HT_OFF  (68 * XST_STR)                  // 17748: [66 t][133], data t = s+1
#define AB_OFF  26528                           // 2 x [256][36] raw weight tiles
#define ABUF_FL 9216
#define PR_OFF  (AB_OFF + ABUF_FL)              // 35744: K-split partials (8192 fl)
#define PART_OFF (AB_OFF + 2*ABUF_FL)           // 44960
#define SMEM_FL  (PART_OFF + 512)               // 45472 fl = 181888 B

__device__ __forceinline__ uint32_t smem_u32(const void* p) {
    uint32_t a;
    asm("{ .reg .u64 t; cvta.to.shared.u64 t, %1; cvt.u32.u64 %0, t; }"
        : "=r"(a) : "l"(p));
    return a;
}
__device__ __forceinline__ float leaky(float v) { return (v > 0.f) ? v : 0.01f * v; }
__device__ __forceinline__ float sigmoidf_fast(float v) {
    return 1.0f / (1.0f + __expf(-v));
}
__device__ __forceinline__ void cpa16(uint32_t dst, const void* src) {
    asm volatile("cp.async.cg.shared.global [%0], [%1], 16;" :: "r"(dst), "l"(src));
}
#define CP_COMMIT() asm volatile("cp.async.commit_group;" ::: "memory")
#define CP_WAIT0()  asm volatile("cp.async.wait_group 0;" ::: "memory")
#define CP_WAIT1()  asm volatile("cp.async.wait_group 1;" ::: "memory")

// D[16x8] += A[16x8] * B[8x8]  (tf32: HW truncates raw fp32 operand bits)
__device__ __forceinline__ void mma8(float* d, const uint32_t* a,
                                     uint32_t b0, uint32_t b1) {
    asm volatile(
        "mma.sync.aligned.m16n8k8.row.col.f32.tf32.tf32.f32 "
        "{%0,%1,%2,%3}, {%4,%5,%6,%7}, {%8,%9}, {%0,%1,%2,%3};"
        : "+f"(d[0]), "+f"(d[1]), "+f"(d[2]), "+f"(d[3])
        : "r"(a[0]), "r"(a[1]), "r"(a[2]), "r"(a[3]), "r"(b0), "r"(b1));
}

__device__ __forceinline__ float pool_val(int s, float x0, float x1, float x2,
                                          float x3, float x4, float l1, float l2) {
    float avg3 = (x1 + x2 + x3) * (1.0f / 3.0f);
    float avg5 = (x0 + x1 + x2 + x3 + x4) * 0.2f;
    float mx3 = x2;
    if (s >= 1)  mx3 = fmaxf(mx3, x1);
    if (s <= 62) mx3 = fmaxf(mx3, x3);
    float mx5 = mx3;
    if (s >= 2)  mx5 = fmaxf(mx5, x0);
    if (s <= 61) mx5 = fmaxf(mx5, x4);
    return (avg3 + mx3) * sigmoidf_fast(l1) + (avg5 + mx5) * sigmoidf_fast(l2);
}

__global__ void __launch_bounds__(NT, 1)
mtb_mma4_kernel(const float* __restrict__ x,
                const float* __restrict__ W1a,
                const float* __restrict__ W1b,
                const float* __restrict__ W2a,
                const float* __restrict__ W2b,
                float* __restrict__ out)
{
    extern __shared__ float smem[];
    float* xst = smem + XST_OFF;     // time-major x, exact fp32
    float* ht  = smem + HT_OFF;      // time-major h (raw fp32), cols 0..63 h1, 64..127 h2
    const uint32_t ab_addr = smem_u32(smem + AB_OFF);

    const int tid = threadIdx.x;
    const int wid = tid >> 5;
    const int l   = tid & 31;
    const int b   = blockIdx.x >> 4;
    const int p   = blockIdx.x & 15;

    // ---- zero pads ----
    if (tid < 256) {
        xst[0 * XST_STR + tid] = 0.f;
        xst[1 * XST_STR + tid] = 0.f;
        xst[66 * XST_STR + tid] = 0.f;
        xst[67 * XST_STR + tid] = 0.f;
    }
    if (tid < 128) {
        ht[0 * HT_STR + tid] = 0.f;
        ht[65 * HT_STR + tid] = 0.f;
    }

    const float* Wa1 = W1a + (size_t)p * (64 * CH * 3);   // [64][768]
    const float* Wa2 = W2a + (size_t)p * (64 * CH * 3);
    const float* Wb1 = W1b + (size_t)p * (CH * 64);       // [256][64]
    const float* Wb2 = W2b + (size_t)p * (CH * 192);      // [256][192]

    // ---- prefetch phase-1 chunk 0 (overlaps x load) ----
    #pragma unroll
    for (int it = 0; it < 2; it++) {
        int idx = it * NT + tid;
        int row = idx >> 3, col4 = idx & 7;
        const float* src = ((row < 64) ? (Wa1 + row * 768)
                                       : (Wa2 + (row - 64) * 768)) + col4 * 4;
        cpa16(ab_addr + (uint32_t)(row * A_STR + col4 * 4) * 4u, src);
    }
    CP_COMMIT();

    // ---- load x slice (exact fp32, time-major): xst[s+2][c] ----
    {
        const int c  = tid & 255;
        const int sh = tid >> 8;
        const float* xb = x + (size_t)b * (SEQ * CH * PARTS) + p + (size_t)c * PARTS;
        float* xcol = xst + (sh * 32 + 2) * XST_STR + c;
        #pragma unroll 8
        for (int s = 0; s < 32; s++)
            xcol[s * XST_STR] = xb[(size_t)(sh * 32 + s) * (CH * PARTS)];
    }

    // ================= Phase 1: D1[128 r][64 s], K=768 (kk = c*3+k) =============
    const int ks1   = wid >> 3;
    const int mrow1 = (wid >> 1) & 3;
    const int nh1   = wid & 1;

    float acc[2][4][4];
    #pragma unroll
    for (int i = 0; i < 2; i++)
        #pragma unroll
        for (int j = 0; j < 4; j++)
            #pragma unroll
            for (int t = 0; t < 4; t++) acc[i][j][t] = 0.f;

    for (int g = 0; g < 24; g++) {
        const int buf = g & 1;
        if (g + 1 < 24) {
            const int nb = buf ^ 1;
            #pragma unroll
            for (int it = 0; it < 2; it++) {
                int idx = it * NT + tid;
                int row = idx >> 3, col4 = idx & 7;
                const float* src = ((row < 64) ? (Wa1 + row * 768)
                                               : (Wa2 + (row - 64) * 768))
                                   + (g + 1) * 32 + col4 * 4;
                cpa16(ab_addr + (uint32_t)(nb * ABUF_FL + row * A_STR + col4 * 4) * 4u, src);
            }
            CP_COMMIT();
            CP_WAIT1();
        } else {
            CP_WAIT0();
        }
        __syncthreads();

        const float* Ar = smem + AB_OFF + buf * ABUF_FL;
        #pragma unroll
        for (int q2 = 0; q2 < 2; q2++) {
            int qq   = ks1 * 2 + q2;
            int kloc = qq * 8 + (l & 3);
            int kg   = g * 32 + kloc;
            int c0 = kg / 3,       k0 = kg - 3 * c0;
            int c1 = (kg + 4) / 3, k1 = (kg + 4) - 3 * c1;
            const float* bp0 = xst + (nh1 * 32 + (l >> 2) + k0 + 1) * XST_STR + c0;
            const float* bp1 = xst + (nh1 * 32 + (l >> 2) + k1 + 1) * XST_STR + c1;
            uint32_t a[2][4];
            #pragma unroll
            for (int msub = 0; msub < 2; msub++) {
                const float* ap = Ar + (mrow1 * 32 + msub * 16 + (l >> 2)) * A_STR + kloc;
                a[msub][0] = __float_as_uint(ap[0]);
                a[msub][1] = __float_as_uint(ap[8 * A_STR]);
                a[msub][2] = __float_as_uint(ap[4]);
                a[msub][3] = __float_as_uint(ap[8 * A_STR + 4]);
            }
            #pragma unroll
            for (int n8 = 0; n8 < 4; n8++) {
                uint32_t b0 = __float_as_uint(bp0[n8 * 8 * XST_STR]);
                uint32_t b1 = __float_as_uint(bp1[n8 * 8 * XST_STR]);
                mma8(acc[0][n8], a[0], b0, b1);
                mma8(acc[1][n8], a[1], b0, b1);
            }
        }
        __syncthreads();
    }

    // ---- K-split merge: ks1==1 warps publish partials ----
    {
        float4* pb = reinterpret_cast<float4*>(smem + PR_OFF);
        if (ks1 == 1) {
            int base = ((wid - 8) * 32 + l) * 8;
            #pragma unroll
            for (int msub = 0; msub < 2; msub++)
                #pragma unroll
                for (int n8 = 0; n8 < 4; n8++)
                    pb[base + msub * 4 + n8] =
                        make_float4(acc[msub][n8][0], acc[msub][n8][1],
                                    acc[msub][n8][2], acc[msub][n8][3]);
        }
    }
    __syncthreads();

    // ---- prefetch phase-2 tile 0 (Wb1 cols 0..31) into buf 0 ----
    #pragma unroll
    for (int it = 0; it < 4; it++) {
        int idx = it * NT + tid;
        int row = idx >> 3, col4 = idx & 7;
        cpa16(ab_addr + (uint32_t)(row * A_STR + col4 * 4) * 4u,
              Wb1 + row * 64 + col4 * 4);
    }
    CP_COMMIT();

    // ---- epilogue 1 (ks1==0 warps): merge + leaky -> ht (raw fp32, time-major) ----
    if (ks1 == 0) {
        const float4* pb = reinterpret_cast<const float4*>(smem + PR_OFF);
        int base = (wid * 32 + l) * 8;
        #pragma unroll
        for (int msub = 0; msub < 2; msub++) {
            #pragma unroll
            for (int n8 = 0; n8 < 4; n8++) {
                float4 t = pb[base + msub * 4 + n8];
                float d0 = acc[msub][n8][0] + t.x;
                float d1 = acc[msub][n8][1] + t.y;
                float d2 = acc[msub][n8][2] + t.z;
                float d3 = acc[msub][n8][3] + t.w;
                int r    = mrow1 * 32 + msub * 16 + (l >> 2);
                int scol = nh1 * 32 + n8 * 8 + 2 * (l & 3);
                float* h0 = ht + (scol + 1) * HT_STR + r;
                float* h1 = ht + (scol + 2) * HT_STR + r;
                h0[0] = leaky(d0);
                h1[0] = leaky(d1);
                h0[8] = leaky(d2);
                h1[8] = leaky(d3);
            }
        }
    }
    __syncthreads();

    // ================= Phase 2: logits1 (K=64) + logits2 (K=192) ===============
    const int mrow2 = wid >> 1;     // 0..7 over 256 c-rows
    const int nh2   = wid & 1;

    float acc1[2][4][4], acc2[2][4][4];
    #pragma unroll
    for (int i = 0; i < 2; i++)
        #pragma unroll
        for (int j = 0; j < 4; j++)
            #pragma unroll
            for (int t = 0; t < 4; t++) { acc1[i][j][t] = 0.f; acc2[i][j][t] = 0.f; }

    for (int j = 0; j < 8; j++) {
        const int buf = j & 1;
        if (j + 1 < 8) {
            const int nb = buf ^ 1;
            const int jn = j + 1;
            const float* base = (jn < 2) ? Wb1 : Wb2;
            const int rstr    = (jn < 2) ? 64 : 192;
            const int koff    = (jn < 2) ? jn * 32 : (jn - 2) * 32;
            #pragma unroll
            for (int it = 0; it < 4; it++) {
                int idx = it * NT + tid;
                int row = idx >> 3, col4 = idx & 7;
                cpa16(ab_addr + (uint32_t)(nb * ABUF_FL + row * A_STR + col4 * 4) * 4u,
                      base + row * rstr + koff + col4 * 4);
            }
            CP_COMMIT();
            CP_WAIT1();
        } else {
            CP_WAIT0();
        }
        __syncthreads();

        const float* Ar = smem + AB_OFF + buf * ABUF_FL;
        if (j < 2) {
            // branch 1: B = h1 (ht cols 0..63), k-row = h directly
            #pragma unroll
            for (int qq = 0; qq < 4; qq++) {
                int kloc = qq * 8 + (l & 3);
                int h    = j * 32 + kloc;
                const float* bp = ht + (nh2 * 32 + (l >> 2) + 1) * HT_STR + h;
                uint32_t a[2][4];
                #pragma unroll
                for (int msub = 0; msub < 2; msub++) {
                    const float* ap = Ar + (mrow2 * 32 + msub * 16 + (l >> 2)) * A_STR + kloc;
                    a[msub][0] = __float_as_uint(ap[0]);
                    a[msub][1] = __float_as_uint(ap[8 * A_STR]);
                    a[msub][2] = __float_as_uint(ap[4]);
                    a[msub][3] = __float_as_uint(ap[8 * A_STR + 4]);
                }
                #pragma unroll
                for (int n8 = 0; n8 < 4; n8++) {
                    uint32_t b0 = __float_as_uint(bp[n8 * 8 * HT_STR]);
                    uint32_t b1 = __float_as_uint(bp[n8 * 8 * HT_STR + 4]);
                    mma8(acc1[0][n8], a[0], b0, b1);
                    mma8(acc1[1][n8], a[1], b0, b1);
                }
            }
        } else {
            // branch 2: B = h2 shifted windows (ht cols 64..127), kk = h*3+k
            const int gj = j - 2;
            #pragma unroll
            for (int qq = 0; qq < 4; qq++) {
                int kloc = qq * 8 + (l & 3);
                int kg   = gj * 32 + kloc;
                int h0 = kg / 3,       k0 = kg - 3 * h0;
                int h1 = (kg + 4) / 3, k1 = (kg + 4) - 3 * h1;
                const float* bp0 = ht + (nh2 * 32 + (l >> 2) + k0) * HT_STR + 64 + h0;
                const float* bp1 = ht + (nh2 * 32 + (l >> 2) + k1) * HT_STR + 64 + h1;
                uint32_t a[2][4];
                #pragma unroll
                for (int msub = 0; msub < 2; msub++) {
                    const float* ap = Ar + (mrow2 * 32 + msub * 16 + (l >> 2)) * A_STR + kloc;
                    a[msub][0] = __float_as_uint(ap[0]);
                    a[msub][1] = __float_as_uint(ap[8 * A_STR]);
                    a[msub][2] = __float_as_uint(ap[4]);
                    a[msub][3] = __float_as_uint(ap[8 * A_STR + 4]);
                }
                #pragma unroll
                for (int n8 = 0; n8 < 4; n8++) {
                    uint32_t b0 = __float_as_uint(bp0[n8 * 8 * HT_STR]);
                    uint32_t b1 = __float_as_uint(bp1[n8 * 8 * HT_STR]);
                    mma8(acc2[0][n8], a[0], b0, b1);
                    mma8(acc2[1][n8], a[1], b0, b1);
                }
            }
        }
        __syncthreads();
    }

    // ---- epilogue 2: pools + sigmoid gates + combine + temporal max ----
    float rmax[4] = {-INFINITY, -INFINITY, -INFINITY, -INFINITY};
    #pragma unroll
    for (int msub = 0; msub < 2; msub++) {
        #pragma unroll
        for (int n8 = 0; n8 < 4; n8++) {
            int R0 = mrow2 * 32 + msub * 16 + (l >> 2);
            int s0 = nh2 * 32 + n8 * 8 + 2 * (l & 3);
            #pragma unroll
            for (int rh = 0; rh < 2; rh++) {
                int c = R0 + rh * 8;
                const float* xr = xst + s0 * XST_STR + c;
                float w0 = xr[0],            w1 = xr[XST_STR];
                float w2 = xr[2 * XST_STR],  w3 = xr[3 * XST_STR];
                float w4 = xr[4 * XST_STR],  w5 = xr[5 * XST_STR];
                float v0 = pool_val(s0, w0, w1, w2, w3, w4,
                                    acc1[msub][n8][rh * 2], acc2[msub][n8][rh * 2]);
                float v1 = pool_val(s0 + 1, w1, w2, w3, w4, w5,
                                    acc1[msub][n8][rh * 2 + 1], acc2[msub][n8][rh * 2 + 1]);
                rmax[msub * 2 + rh] = fmaxf(rmax[msub * 2 + rh], fmaxf(v0, v1));
            }
        }
    }
    #pragma unroll
    for (int off = 1; off <= 2; off <<= 1) {
        #pragma unroll
        for (int i = 0; i < 4; i++)
            rmax[i] = fmaxf(rmax[i], __shfl_xor_sync(0xffffffffu, rmax[i], off));
    }
    {
        int idx = l & 3;
        float v = (idx == 0) ? rmax[0] : (idx == 1) ? rmax[1]
                 : (idx == 2) ? rmax[2] : rmax[3];
        int row = mrow2 * 32 + 16 * (idx >> 1) + 8 * (idx & 1) + (l >> 2);
        smem[PART_OFF + nh2 * 256 + row] = v;
    }
    __syncthreads();
    if (tid < 256)
        out[(size_t)blockIdx.x * CH + tid] =
            fmaxf(smem[PART_OFF + tid], smem[PART_OFF + 256 + tid]);
}

extern "C" void kernel_launch(void* const* d_in, const int* in_sizes, int n_in,
                              void* d_out, int out_size)
{
    const float* x   = (const float*)d_in[0];
    const float* W1a = (const float*)d_in[1];
    const float* W1b = (const float*)d_in[2];
    const float* W2a = (const float*)d_in[3];
    const float* W2b = (const float*)d_in[4];
    float* out = (float*)d_out;

    const int smem_bytes = SMEM_FL * (int)sizeof(float);   // 181888
    cudaFuncSetAttribute(mtb_mma4_kernel, cudaFuncAttributeMaxDynamicSharedMemorySize,
                         smem_bytes);
    mtb_mma4_kernel<<<BB * PARTS, NT, smem_bytes>>>(x, W1a, W1b, W2a, W2b, out);
}

// round 17
// speedup vs baseline: 1.1073x; 1.0269x over previous
#include <cuda_runtime.h>
#include <math.h>
#include <stdint.h>

#define BB    128
#define SEQ   64
#define CH    256
#define PARTS 16
#define NT    512

#define XST_STR 261                 // 261 % 32 = 5 -> conflict-free quad reads
#define HT_STR  133                 // 133 % 32 = 5
#define A_STR   36                  // phase-2 tiles [256][36], 36 % 32 = 4
#define A1_STR  68                  // phase-1 tiles [128][68], 68 % 32 = 4

#define XST_OFF 0                               // [68 t][261], data t = s+2
#define HT_OFF  (68 * XST_STR)                  // 17748: [66 t][133], data t = s+1
#define AB_OFF  26528                           // 2 x weight stage buffers
#define ABUF_FL 9216                            // >= max(128*68=8704, 256*36=9216)
#define PR_OFF  (AB_OFF + ABUF_FL)              // K-split partials (8192 fl)
#define PART_OFF (AB_OFF + 2*ABUF_FL)           // 44960
#define SMEM_FL  (PART_OFF + 512)               // 45472 fl = 181888 B

__device__ __forceinline__ uint32_t smem_u32(const void* p) {
    uint32_t a;
    asm("{ .reg .u64 t; cvta.to.shared.u64 t, %1; cvt.u32.u64 %0, t; }"
        : "=r"(a) : "l"(p));
    return a;
}
__device__ __forceinline__ float leaky(float v) { return (v > 0.f) ? v : 0.01f * v; }
__device__ __forceinline__ float sigmoidf_fast(float v) {
    return 1.0f / (1.0f + __expf(-v));
}
__device__ __forceinline__ void cpa16(uint32_t dst, const void* src) {
    asm volatile("cp.async.cg.shared.global [%0], [%1], 16;" :: "r"(dst), "l"(src));
}
#define CP_COMMIT() asm volatile("cp.async.commit_group;" ::: "memory")
#define CP_WAIT0()  asm volatile("cp.async.wait_group 0;" ::: "memory")
#define CP_WAIT1()  asm volatile("cp.async.wait_group 1;" ::: "memory")

// D[16x8] += A[16x8] * B[8x8]  (tf32: HW truncates raw fp32 operand bits)
__device__ __forceinline__ void mma8(float* d, const uint32_t* a,
                                     uint32_t b0, uint32_t b1) {
    asm volatile(
        "mma.sync.aligned.m16n8k8.row.col.f32.tf32.tf32.f32 "
        "{%0,%1,%2,%3}, {%4,%5,%6,%7}, {%8,%9}, {%0,%1,%2,%3};"
        : "+f"(d[0]), "+f"(d[1]), "+f"(d[2]), "+f"(d[3])
        : "r"(a[0]), "r"(a[1]), "r"(a[2]), "r"(a[3]), "r"(b0), "r"(b1));
}

__device__ __forceinline__ float pool_val(int s, float x0, float x1, float x2,
                                          float x3, float x4, float l1, float l2) {
    float avg3 = (x1 + x2 + x3) * (1.0f / 3.0f);
    float avg5 = (x0 + x1 + x2 + x3 + x4) * 0.2f;
    float mx3 = x2;
    if (s >= 1)  mx3 = fmaxf(mx3, x1);
    if (s <= 62) mx3 = fmaxf(mx3, x3);
    float mx5 = mx3;
    if (s >= 2)  mx5 = fmaxf(mx5, x0);
    if (s <= 61) mx5 = fmaxf(mx5, x4);
    return (avg3 + mx3) * sigmoidf_fast(l1) + (avg5 + mx5) * sigmoidf_fast(l2);
}

__global__ void __launch_bounds__(NT, 1)
mtb_mma5_kernel(const float* __restrict__ x,
                const float* __restrict__ W1a,
                const float* __restrict__ W1b,
                const float* __restrict__ W2a,
                const float* __restrict__ W2b,
                float* __restrict__ out)
{
    extern __shared__ float smem[];
    float* xst = smem + XST_OFF;     // time-major x, exact fp32
    float* ht  = smem + HT_OFF;      // time-major h (raw fp32), cols 0..63 h1, 64..127 h2
    const uint32_t ab_addr = smem_u32(smem + AB_OFF);

    const int tid = threadIdx.x;
    const int wid = tid >> 5;
    const int l   = tid & 31;
    const int b   = blockIdx.x >> 4;
    const int p   = blockIdx.x & 15;

    // ---- zero pads ----
    if (tid < 256) {
        xst[0 * XST_STR + tid] = 0.f;
        xst[1 * XST_STR + tid] = 0.f;
        xst[66 * XST_STR + tid] = 0.f;
        xst[67 * XST_STR + tid] = 0.f;
    }
    if (tid < 128) {
        ht[0 * HT_STR + tid] = 0.f;
        ht[65 * HT_STR + tid] = 0.f;
    }

    const float* Wa1 = W1a + (size_t)p * (64 * CH * 3);   // [64][768]
    const float* Wa2 = W2a + (size_t)p * (64 * CH * 3);
    const float* Wb1 = W1b + (size_t)p * (CH * 64);       // [256][64]
    const float* Wb2 = W2b + (size_t)p * (CH * 192);      // [256][192]

    // ---- prefetch phase-1 chunk 0 ([128][64], overlaps x load) ----
    #pragma unroll
    for (int it = 0; it < 4; it++) {
        int idx = it * NT + tid;
        int row = idx >> 4, col4 = idx & 15;
        const float* src = ((row < 64) ? (Wa1 + row * 768)
                                       : (Wa2 + (row - 64) * 768)) + col4 * 4;
        cpa16(ab_addr + (uint32_t)(row * A1_STR + col4 * 4) * 4u, src);
    }
    CP_COMMIT();

    // ---- load x slice (exact fp32, time-major): xst[s+2][c] ----
    {
        const int c  = tid & 255;
        const int sh = tid >> 8;
        const float* xb = x + (size_t)b * (SEQ * CH * PARTS) + p + (size_t)c * PARTS;
        float* xcol = xst + (sh * 32 + 2) * XST_STR + c;
        #pragma unroll 8
        for (int s = 0; s < 32; s++)
            xcol[s * XST_STR] = xb[(size_t)(sh * 32 + s) * (CH * PARTS)];
    }

    // ================= Phase 1: D1[128 r][64 s], K=768 (kk = c*3+k) =============
    // 12 chunks of K=64. warp: ks1 (K-split of 4 octets), mrow1 (m32), nh1 (n32)
    const int ks1   = wid >> 3;
    const int mrow1 = (wid >> 1) & 3;
    const int nh1   = wid & 1;

    float acc[2][4][4];
    #pragma unroll
    for (int i = 0; i < 2; i++)
        #pragma unroll
        for (int j = 0; j < 4; j++)
            #pragma unroll
            for (int t = 0; t < 4; t++) acc[i][j][t] = 0.f;

    for (int g = 0; g < 12; g++) {
        const int buf = g & 1;
        if (g + 1 < 12) {
            const int nb = buf ^ 1;
            #pragma unroll
            for (int it = 0; it < 4; it++) {
                int idx = it * NT + tid;
                int row = idx >> 4, col4 = idx & 15;
                const float* src = ((row < 64) ? (Wa1 + row * 768)
                                               : (Wa2 + (row - 64) * 768))
                                   + (g + 1) * 64 + col4 * 4;
                cpa16(ab_addr + (uint32_t)(nb * ABUF_FL + row * A1_STR + col4 * 4) * 4u, src);
            }
            CP_COMMIT();
            CP_WAIT1();
        } else {
            CP_WAIT0();
        }
        __syncthreads();

        const float* Ar = smem + AB_OFF + buf * ABUF_FL;
        #pragma unroll
        for (int q2 = 0; q2 < 4; q2++) {
            int qq   = ks1 * 4 + q2;
            int kloc = qq * 8 + (l & 3);
            int kg   = g * 64 + kloc;
            int c0 = kg / 3,       k0 = kg - 3 * c0;
            int c1 = (kg + 4) / 3, k1 = (kg + 4) - 3 * c1;
            const float* bp0 = xst + (nh1 * 32 + (l >> 2) + k0 + 1) * XST_STR + c0;
            const float* bp1 = xst + (nh1 * 32 + (l >> 2) + k1 + 1) * XST_STR + c1;
            uint32_t a[2][4];
            #pragma unroll
            for (int msub = 0; msub < 2; msub++) {
                const float* ap = Ar + (mrow1 * 32 + msub * 16 + (l >> 2)) * A1_STR + kloc;
                a[msub][0] = __float_as_uint(ap[0]);
                a[msub][1] = __float_as_uint(ap[8 * A1_STR]);
                a[msub][2] = __float_as_uint(ap[4]);
                a[msub][3] = __float_as_uint(ap[8 * A1_STR + 4]);
            }
            #pragma unroll
            for (int n8 = 0; n8 < 4; n8++) {
                uint32_t b0 = __float_as_uint(bp0[n8 * 8 * XST_STR]);
                uint32_t b1 = __float_as_uint(bp1[n8 * 8 * XST_STR]);
                mma8(acc[0][n8], a[0], b0, b1);
                mma8(acc[1][n8], a[1], b0, b1);
            }
        }
        __syncthreads();
    }

    // ---- K-split merge: ks1==1 warps publish partials ----
    {
        float4* pb = reinterpret_cast<float4*>(smem + PR_OFF);
        if (ks1 == 1) {
            int base = ((wid - 8) * 32 + l) * 8;
            #pragma unroll
            for (int msub = 0; msub < 2; msub++)
                #pragma unroll
                for (int n8 = 0; n8 < 4; n8++)
                    pb[base + msub * 4 + n8] =
                        make_float4(acc[msub][n8][0], acc[msub][n8][1],
                                    acc[msub][n8][2], acc[msub][n8][3]);
        }
    }
    __syncthreads();

    // ---- prefetch phase-2 tile 0 (Wb1 cols 0..31) into buf 0 ----
    #pragma unroll
    for (int it = 0; it < 4; it++) {
        int idx = it * NT + tid;
        int row = idx >> 3, col4 = idx & 7;
        cpa16(ab_addr + (uint32_t)(row * A_STR + col4 * 4) * 4u,
              Wb1 + row * 64 + col4 * 4);
    }
    CP_COMMIT();

    // ---- epilogue 1 (ks1==0 warps): merge + leaky -> ht (raw fp32, time-major) ----
    if (ks1 == 0) {
        const float4* pb = reinterpret_cast<const float4*>(smem + PR_OFF);
        int base = (wid * 32 + l) * 8;
        #pragma unroll
        for (int msub = 0; msub < 2; msub++) {
            #pragma unroll
            for (int n8 = 0; n8 < 4; n8++) {
                float4 t = pb[base + msub * 4 + n8];
                float d0 = acc[msub][n8][0] + t.x;
                float d1 = acc[msub][n8][1] + t.y;
                float d2 = acc[msub][n8][2] + t.z;
                float d3 = acc[msub][n8][3] + t.w;
                int r    = mrow1 * 32 + msub * 16 + (l >> 2);
                int scol = nh1 * 32 + n8 * 8 + 2 * (l & 3);
                float* h0 = ht + (scol + 1) * HT_STR + r;
                float* h1 = ht + (scol + 2) * HT_STR + r;
                h0[0] = leaky(d0);
                h1[0] = leaky(d1);
                h0[8] = leaky(d2);
                h1[8] = leaky(d3);
            }
        }
    }
    __syncthreads();

    // ================= Phase 2: logits1 (K=64) + logits2 (K=192) ===============
    const int mrow2 = wid >> 1;     // 0..7 over 256 c-rows
    const int nh2   = wid & 1;

    float acc1[2][4][4], acc2[2][4][4];
    #pragma unroll
    for (int i = 0; i < 2; i++)
        #pragma unroll
        for (int j = 0; j < 4; j++)
            #pragma unroll
            for (int t = 0; t < 4; t++) { acc1[i][j][t] = 0.f; acc2[i][j][t] = 0.f; }

    for (int j = 0; j < 8; j++) {
        const int buf = j & 1;
        if (j + 1 < 8) {
            const int nb = buf ^ 1;
            const int jn = j + 1;
            const float* base = (jn < 2) ? Wb1 : Wb2;
            const int rstr    = (jn < 2) ? 64 : 192;
            const int koff    = (jn < 2) ? jn * 32 : (jn - 2) * 32;
            #pragma unroll
            for (int it = 0; it < 4; it++) {
                int idx = it * NT + tid;
                int row = idx >> 3, col4 = idx & 7;
                cpa16(ab_addr + (uint32_t)(nb * ABUF_FL + row * A_STR + col4 * 4) * 4u,
                      base + row * rstr + koff + col4 * 4);
            }
            CP_COMMIT();
            CP_WAIT1();
        } else {
            CP_WAIT0();
        }
        __syncthreads();

        const float* Ar = smem + AB_OFF + buf * ABUF_FL;
        if (j < 2) {
            // branch 1: B = h1 (ht cols 0..63), k-row = h directly
            #pragma unroll
            for (int qq = 0; qq < 4; qq++) {
                int kloc = qq * 8 + (l & 3);
                int h    = j * 32 + kloc;
                const float* bp = ht + (nh2 * 32 + (l >> 2) + 1) * HT_STR + h;
                uint32_t a[2][4];
                #pragma unroll
                for (int msub = 0; msub < 2; msub++) {
                    const float* ap = Ar + (mrow2 * 32 + msub * 16 + (l >> 2)) * A_STR + kloc;
                    a[msub][0] = __float_as_uint(ap[0]);
                    a[msub][1] = __float_as_uint(ap[8 * A_STR]);
                    a[msub][2] = __float_as_uint(ap[4]);
                    a[msub][3] = __float_as_uint(ap[8 * A_STR + 4]);
                }
                #pragma unroll
                for (int n8 = 0; n8 < 4; n8++) {
                    uint32_t b0 = __float_as_uint(bp[n8 * 8 * HT_STR]);
                    uint32_t b1 = __float_as_uint(bp[n8 * 8 * HT_STR + 4]);
                    mma8(acc1[0][n8], a[0], b0, b1);
                    mma8(acc1[1][n8], a[1], b0, b1);
                }
            }
        } else {
            // branch 2: B = h2 shifted windows (ht cols 64..127), kk = h*3+k
            const int gj = j - 2;
            #pragma unroll
            for (int qq = 0; qq < 4; qq++) {
                int kloc = qq * 8 + (l & 3);
                int kg   = gj * 32 + kloc;
                int h0 = kg / 3,       k0 = kg - 3 * h0;
                int h1 = (kg + 4) / 3, k1 = (kg + 4) - 3 * h1;
                const float* bp0 = ht + (nh2 * 32 + (l >> 2) + k0) * HT_STR + 64 + h0;
                const float* bp1 = ht + (nh2 * 32 + (l >> 2) + k1) * HT_STR + 64 + h1;
                uint32_t a[2][4];
                #pragma unroll
                for (int msub = 0; msub < 2; msub++) {
                    const float* ap = Ar + (mrow2 * 32 + msub * 16 + (l >> 2)) * A_STR + kloc;
                    a[msub][0] = __float_as_uint(ap[0]);
                    a[msub][1] = __float_as_uint(ap[8 * A_STR]);
                    a[msub][2] = __float_as_uint(ap[4]);
                    a[msub][3] = __float_as_uint(ap[8 * A_STR + 4]);
                }
                #pragma unroll
                for (int n8 = 0; n8 < 4; n8++) {
                    uint32_t b0 = __float_as_uint(bp0[n8 * 8 * HT_STR]);
                    uint32_t b1 = __float_as_uint(bp1[n8 * 8 * HT_STR]);
                    mma8(acc2[0][n8], a[0], b0, b1);
                    mma8(acc2[1][n8], a[1], b0, b1);
                }
            }
        }
        __syncthreads();
    }

    // ---- epilogue 2: pools + sigmoid gates + combine + temporal max ----
    float rmax[4] = {-INFINITY, -INFINITY, -INFINITY, -INFINITY};
    #pragma unroll
    for (int msub = 0; msub < 2; msub++) {
        #pragma unroll
        for (int n8 = 0; n8 < 4; n8++) {
            int R0 = mrow2 * 32 + msub * 16 + (l >> 2);
            int s0 = nh2 * 32 + n8 * 8 + 2 * (l & 3);
            #pragma unroll
            for (int rh = 0; rh < 2; rh++) {
                int c = R0 + rh * 8;
                const float* xr = xst + s0 * XST_STR + c;
                float w0 = xr[0],            w1 = xr[XST_STR];
                float w2 = xr[2 * XST_STR],  w3 = xr[3 * XST_STR];
                float w4 = xr[4 * XST_STR],  w5 = xr[5 * XST_STR];
                float v0 = pool_val(s0, w0, w1, w2, w3, w4,
                                    acc1[msub][n8][rh * 2], acc2[msub][n8][rh * 2]);
                float v1 = pool_val(s0 + 1, w1, w2, w3, w4, w5,
                                    acc1[msub][n8][rh * 2 + 1], acc2[msub][n8][rh * 2 + 1]);
                rmax[msub * 2 + rh] = fmaxf(rmax[msub * 2 + rh], fmaxf(v0, v1));
            }
        }
    }
    #pragma unroll
    for (int off = 1; off <= 2; off <<= 1) {
        #pragma unroll
        for (int i = 0; i < 4; i++)
            rmax[i] = fmaxf(rmax[i], __shfl_xor_sync(0xffffffffu, rmax[i], off));
    }
    {
        int idx = l & 3;
        float v = (idx == 0) ? rmax[0] : (idx == 1) ? rmax[1]
                 : (idx == 2) ? rmax[2] : rmax[3];
        int row = mrow2 * 32 + 16 * (idx >> 1) + 8 * (idx & 1) + (l >> 2);
        smem[PART_OFF + nh2 * 256 + row] = v;
    }
    __syncthreads();
    if (tid < 256)
        out[(size_t)blockIdx.x * CH + tid] =
            fmaxf(smem[PART_OFF + tid], smem[PART_OFF + 256 + tid]);
}

extern "C" void kernel_launch(void* const* d_in, const int* in_sizes, int n_in,
                              void* d_out, int out_size)
{
    const float* x   = (const float*)d_in[0];
    const float* W1a = (const float*)d_in[1];
    const float* W1b = (const float*)d_in[2];
    const float* W2a = (const float*)d_in[3];
    const float* W2b = (const float*)d_in[4];
    float* out = (float*)d_out;

    const int smem_bytes = SMEM_FL * (int)sizeof(float);   // 181888
    cudaFuncSetAttribute(mtb_mma5_kernel, cudaFuncAttributeMaxDynamicSharedMemorySize,
                         smem_bytes);
    mtb_mma5_kernel<<<BB * PARTS, NT, smem_bytes>>>(x, W1a, W1b, W2a, W2b, out);
}